// round 2
// baseline (speedup 1.0000x reference)
#include <cuda_runtime.h>

#define BT 8192
#define T1 50
#define T2 100

#define G1 32
#define G2 16
#define HB_P 68     // 68 mod 32 = 4 -> conflict-free lane-strided rows, 272B = 16B-aligned
#define GA_P 260    // gate buffer row pad
#define WIH_P 132   // 132 mod 32 = 4, 528B = 16B-aligned

// inter-kernel scratch: layer1 output sequence [B][T1][128]
static __device__ float g_seq1[BT * T1 * 128];

__device__ __forceinline__ float fsig(float x) {
    return __fdividef(1.f, 1.f + __expf(-x));
}
__device__ __forceinline__ float ftanh_(float x) {
    float e = __expf(-2.f * fabsf(x));
    float r = __fdividef(1.f - e, 1.f + e);
    return copysignf(r, x);
}
__device__ __forceinline__ float dot4acc(float4 w, float4 h, float a) {
    a = fmaf(w.x, h.x, a); a = fmaf(w.y, h.y, a);
    a = fmaf(w.z, h.z, a); return fmaf(w.w, h.w, a);
}

// ---------------------------------------------------------------------------
// Kernel 1: fc1 + bidirectional LSTM layer 1 (input dim 1) -> g_seq1
// One CTA = G1 samples, 256 threads = 256 gates. Whh row in registers.
// ---------------------------------------------------------------------------
__global__ __launch_bounds__(256, 2)
void k_layer1(const float* __restrict__ x,
              const float* __restrict__ fc1_w, const float* __restrict__ fc1_b,
              const float* __restrict__ wih_f, const float* __restrict__ whh_f, const float* __restrict__ b_f,
              const float* __restrict__ wih_b, const float* __restrict__ whh_b, const float* __restrict__ b_b)
{
    extern __shared__ float sm[];
    float* gact  = sm;                    // G1*GA_P
    float* hbuf  = gact + G1 * GA_P;      // G1*HB_P
    float* h1buf = hbuf + G1 * HB_P;      // G1*T1

    const int tid  = threadIdx.x;
    const int base = blockIdx.x * G1;
    const int g    = tid;
    const int j    = tid & 63, q = tid >> 6;

    // fc1: h1[s][t] = x[s] . fc1_w[t] + fc1_b[t]
    for (int idx = tid; idx < G1 * T1; idx += 256) {
        int s = idx / T1, t = idx - s * T1;
        const float* xr = x + (base + s) * 20;
        const float* wr = fc1_w + t * 20;
        float acc = fc1_b[t];
        #pragma unroll
        for (int i = 0; i < 20; i++) acc = fmaf(xr[i], wr[i], acc);
        h1buf[s * T1 + t] = acc;
    }

    for (int d = 0; d < 2; d++) {
        const float* whh = d ? whh_b : whh_f;
        const float* wih = d ? wih_b : wih_f;
        const float* bg  = d ? b_b   : b_f;

        __syncthreads();
        for (int idx = tid; idx < G1 * HB_P; idx += 256) hbuf[idx] = 0.f;

        // weight-stationary: this thread's Whh row in registers
        float4 wv[16];
        const float4* wgp = (const float4*)(whh + g * 64);
        #pragma unroll
        for (int kc = 0; kc < 16; kc++) wv[kc] = __ldg(wgp + kc);
        const float wihg = __ldg(wih + g);
        const float bsg  = __ldg(bg + g);

        float c_reg[8];
        #pragma unroll
        for (int i = 0; i < 8; i++) c_reg[i] = 0.f;
        __syncthreads();

        const bool tanh_gate = ((g >> 6) == 2);

        for (int tt = 0; tt < T1; tt++) {
            const int t = d ? (T1 - 1 - tt) : tt;

            // gate pre-activations for all G1 samples.
            // 2 samples per group: keeps <=8 live float4 temporaries so the
            // 128-reg cap (occupancy 2) holds without local spills.
            for (int sg = 0; sg < G1; sg += 2) {
                float a0 = fmaf(h1buf[(sg + 0) * T1 + t], wihg, bsg);
                float a1 = fmaf(h1buf[(sg + 1) * T1 + t], wihg, bsg);
                #pragma unroll
                for (int kc = 0; kc < 16; kc++) {
                    float4 w4 = wv[kc];
                    float4 h0 = *(const float4*)(hbuf + (sg + 0) * HB_P + kc * 4);
                    float4 h1 = *(const float4*)(hbuf + (sg + 1) * HB_P + kc * 4);
                    a0 = dot4acc(w4, h0, a0);
                    a1 = dot4acc(w4, h1, a1);
                }
                gact[(sg + 0) * GA_P + g] = tanh_gate ? ftanh_(a0) : fsig(a0);
                gact[(sg + 1) * GA_P + g] = tanh_gate ? ftanh_(a1) : fsig(a1);
            }
            __syncthreads();

            // state update: thread (j,q) owns hidden unit j of samples s = q+4*si
            #pragma unroll
            for (int si = 0; si < 8; si++) {
                const int s = q + si * 4;
                float gi = gact[s * GA_P + j];
                float gf = gact[s * GA_P + 64 + j];
                float gg = gact[s * GA_P + 128 + j];
                float go = gact[s * GA_P + 192 + j];
                float c  = fmaf(gf, c_reg[si], gi * gg);
                c_reg[si] = c;
                float h = go * ftanh_(c);
                hbuf[s * HB_P + j] = h;
                g_seq1[((base + s) * T1 + t) * 128 + d * 64 + j] = h;
            }
            __syncthreads();
        }
    }
}

// ---------------------------------------------------------------------------
// Kernel 2: bidirectional LSTM layer 2 (input dim 128, with repeat-dedup of
// the input projection) + fc2 + tanh -> out
// ---------------------------------------------------------------------------
__global__ __launch_bounds__(256, 1)
void k_layer2(const float* __restrict__ wih2_f, const float* __restrict__ whh2_f, const float* __restrict__ b2_f,
              const float* __restrict__ wih2_b, const float* __restrict__ whh2_b, const float* __restrict__ b2_b,
              const float* __restrict__ fc2_w, const float* __restrict__ fc2_b,
              float* __restrict__ out)
{
    extern __shared__ float sm[];
    float* wih_s = sm;                      // 256*WIH_P (padded input-proj weights)
    float* xgb   = wih_s + 256 * WIH_P;     // G2*GA_P  (cached input projection)
    float* gact  = xgb  + G2 * GA_P;        // G2*GA_P
    float* hbuf  = gact + G2 * GA_P;        // G2*HB_P
    float* inbuf = hbuf + G2 * HB_P;        // G2*128
    float* outac = inbuf + G2 * 128;        // G2*T2  (fwd fc2 partial dots)
    float* fc2_s = outac + G2 * T2;         // 128

    const int tid  = threadIdx.x;
    const int base = blockIdx.x * G2;
    const int g    = tid;
    const int j    = tid & 63, q = tid >> 6;
    const int wrp  = tid >> 5, lan = tid & 31;

    if (tid < 128) fc2_s[tid] = fc2_w[tid];
    const float fc2b = __ldg(fc2_b);

    for (int d = 0; d < 2; d++) {
        const float* whh = d ? whh2_b : whh2_f;
        const float* wih = d ? wih2_b : wih2_f;
        const float* bg  = d ? b2_b   : b2_f;

        __syncthreads();
        // stage input-projection weights into padded SMEM (conflict-free rows)
        for (int idx = tid; idx < 256 * 128; idx += 256)
            wih_s[(idx >> 7) * WIH_P + (idx & 127)] = wih[idx];
        for (int idx = tid; idx < G2 * HB_P; idx += 256) hbuf[idx] = 0.f;

        // recurrent weights: this thread's Whh row in registers
        float4 wv[16];
        const float4* wgp = (const float4*)(whh + g * 64);
        #pragma unroll
        for (int kc = 0; kc < 16; kc++) wv[kc] = __ldg(wgp + kc);
        const float bsg = __ldg(bg + g);

        float c_reg[4] = {0.f, 0.f, 0.f, 0.f};
        __syncthreads();

        const bool tanh_gate = ((g >> 6) == 2);
        const float* prow = wih_s + g * WIH_P;

        for (int tt = 0; tt < T2; tt++) {
            const int t = d ? (T2 - 1 - tt) : tt;

            // first visit of each repeated pair: load input + compute projection
            if ((tt & 1) == 0) {
                const int m = t >> 1;
                for (int idx = tid; idx < G2 * 32; idx += 256) {
                    int s = idx >> 5, i = idx & 31;
                    ((float4*)inbuf)[idx] =
                        ((const float4*)(g_seq1 + ((base + s) * T1 + m) * 128))[i];
                }
                __syncthreads();
                for (int sg = 0; sg < G2; sg += 4) {
                    float a0 = bsg, a1 = bsg, a2 = bsg, a3 = bsg;
                    #pragma unroll
                    for (int kc = 0; kc < 32; kc++) {
                        float4 w4 = *(const float4*)(prow + kc * 4);
                        float4 i0 = *(const float4*)(inbuf + (sg + 0) * 128 + kc * 4);
                        float4 i1 = *(const float4*)(inbuf + (sg + 1) * 128 + kc * 4);
                        float4 i2 = *(const float4*)(inbuf + (sg + 2) * 128 + kc * 4);
                        float4 i3 = *(const float4*)(inbuf + (sg + 3) * 128 + kc * 4);
                        a0 = dot4acc(w4, i0, a0);
                        a1 = dot4acc(w4, i1, a1);
                        a2 = dot4acc(w4, i2, a2);
                        a3 = dot4acc(w4, i3, a3);
                    }
                    // written & read only by this thread -> no sync needed
                    xgb[(sg + 0) * GA_P + g] = a0;
                    xgb[(sg + 1) * GA_P + g] = a1;
                    xgb[(sg + 2) * GA_P + g] = a2;
                    xgb[(sg + 3) * GA_P + g] = a3;
                }
            }

            // recurrence: gates = xg + Whh @ h
            for (int sg = 0; sg < G2; sg += 4) {
                float a0 = xgb[(sg + 0) * GA_P + g];
                float a1 = xgb[(sg + 1) * GA_P + g];
                float a2 = xgb[(sg + 2) * GA_P + g];
                float a3 = xgb[(sg + 3) * GA_P + g];
                #pragma unroll
                for (int kc = 0; kc < 16; kc++) {
                    float4 w4 = wv[kc];
                    float4 h0 = *(const float4*)(hbuf + (sg + 0) * HB_P + kc * 4);
                    float4 h1 = *(const float4*)(hbuf + (sg + 1) * HB_P + kc * 4);
                    float4 h2 = *(const float4*)(hbuf + (sg + 2) * HB_P + kc * 4);
                    float4 h3 = *(const float4*)(hbuf + (sg + 3) * HB_P + kc * 4);
                    a0 = dot4acc(w4, h0, a0);
                    a1 = dot4acc(w4, h1, a1);
                    a2 = dot4acc(w4, h2, a2);
                    a3 = dot4acc(w4, h3, a3);
                }
                gact[(sg + 0) * GA_P + g] = tanh_gate ? ftanh_(a0) : fsig(a0);
                gact[(sg + 1) * GA_P + g] = tanh_gate ? ftanh_(a1) : fsig(a1);
                gact[(sg + 2) * GA_P + g] = tanh_gate ? ftanh_(a2) : fsig(a2);
                gact[(sg + 3) * GA_P + g] = tanh_gate ? ftanh_(a3) : fsig(a3);
            }
            __syncthreads();

            // state update
            #pragma unroll
            for (int si = 0; si < 4; si++) {
                const int s = q + si * 4;
                float gi = gact[s * GA_P + j];
                float gf = gact[s * GA_P + 64 + j];
                float gg = gact[s * GA_P + 128 + j];
                float go = gact[s * GA_P + 192 + j];
                float c  = fmaf(gf, c_reg[si], gi * gg);
                c_reg[si] = c;
                hbuf[s * HB_P + j] = go * ftanh_(c);
            }
            __syncthreads();

            // fc2 partial dot: warp wrp reduces samples s = wrp, wrp+8
            #pragma unroll
            for (int si = 0; si < 2; si++) {
                const int s = wrp + si * 8;
                float p = hbuf[s * HB_P + lan]      * fc2_s[d * 64 + lan]
                        + hbuf[s * HB_P + 32 + lan] * fc2_s[d * 64 + 32 + lan];
                #pragma unroll
                for (int o = 16; o > 0; o >>= 1)
                    p += __shfl_down_sync(0xffffffffu, p, o);
                if (lan == 0) {
                    if (d == 0) outac[s * T2 + t] = p;
                    else out[(base + s) * T2 + t] = ftanh_(outac[s * T2 + t] + p + fc2b);
                }
            }
        }
    }
}

// ---------------------------------------------------------------------------
extern "C" void kernel_launch(void* const* d_in, const int* in_sizes, int n_in,
                              void* d_out, int out_size)
{
    const float* x    = (const float*)d_in[0];
    const float* fc1w = (const float*)d_in[1];
    const float* fc1b = (const float*)d_in[2];
    const float* r1wf = (const float*)d_in[3];
    const float* r1hf = (const float*)d_in[4];
    const float* r1bf = (const float*)d_in[5];
    const float* r1wb = (const float*)d_in[6];
    const float* r1hb = (const float*)d_in[7];
    const float* r1bb = (const float*)d_in[8];
    const float* r2wf = (const float*)d_in[9];
    const float* r2hf = (const float*)d_in[10];
    const float* r2bf = (const float*)d_in[11];
    const float* r2wb = (const float*)d_in[12];
    const float* r2hb = (const float*)d_in[13];
    const float* r2bb = (const float*)d_in[14];
    const float* fc2w = (const float*)d_in[15];
    const float* fc2b = (const float*)d_in[16];
    float* out = (float*)d_out;

    const size_t SM1 = (size_t)(G1 * GA_P + G1 * HB_P + G1 * T1) * sizeof(float);
    const size_t SM2 = (size_t)(256 * WIH_P + 2 * G2 * GA_P + G2 * HB_P +
                                G2 * 128 + G2 * T2 + 128) * sizeof(float);

    cudaFuncSetAttribute(k_layer1, cudaFuncAttributeMaxDynamicSharedMemorySize, (int)SM1);
    cudaFuncSetAttribute(k_layer2, cudaFuncAttributeMaxDynamicSharedMemorySize, (int)SM2);

    k_layer1<<<BT / G1, 256, SM1>>>(x, fc1w, fc1b, r1wf, r1hf, r1bf, r1wb, r1hb, r1bb);
    k_layer2<<<BT / G2, 256, SM2>>>(r2wf, r2hf, r2bf, r2wb, r2hb, r2bb, fc2w, fc2b, out);
}

// round 3
// speedup vs baseline: 1.0706x; 1.0706x over previous
#include <cuda_runtime.h>

#define BT 8192
#define T1 50
#define T2 100

#define G1 32
#define G2 16
#define HB_P 68     // 68 mod 32 = 4 -> conflict-free lane-strided rows, 272B = 16B-aligned
#define GA_P 260    // gate buffer row pad
#define WT_P 257    // transposed wih rows: [k][g], 257 mod 32 = 1 -> conflict-free staging

// inter-kernel scratch: layer1 output sequence [B][T1][128]
static __device__ float g_seq1[BT * T1 * 128];

__device__ __forceinline__ float fsig(float x) {
    return __fdividef(1.f, 1.f + __expf(-x));
}
__device__ __forceinline__ float ftanh_(float x) {
    float e = __expf(-2.f * fabsf(x));
    float r = __fdividef(1.f - e, 1.f + e);
    return copysignf(r, x);
}
__device__ __forceinline__ float dot4acc(float4 w, float4 h, float a) {
    a = fmaf(w.x, h.x, a); a = fmaf(w.y, h.y, a);
    a = fmaf(w.z, h.z, a); return fmaf(w.w, h.w, a);
}

// ---------------------------------------------------------------------------
// Kernel 1: fc1 + bidirectional LSTM layer 1 (input dim 1) -> g_seq1
// One CTA = G1 samples, 256 threads = 256 gates. Whh row in registers.
// (unchanged: ~76% of its FMA roofline already)
// ---------------------------------------------------------------------------
__global__ __launch_bounds__(256, 2)
void k_layer1(const float* __restrict__ x,
              const float* __restrict__ fc1_w, const float* __restrict__ fc1_b,
              const float* __restrict__ wih_f, const float* __restrict__ whh_f, const float* __restrict__ b_f,
              const float* __restrict__ wih_b, const float* __restrict__ whh_b, const float* __restrict__ b_b)
{
    extern __shared__ float sm[];
    float* gact  = sm;                    // G1*GA_P
    float* hbuf  = gact + G1 * GA_P;      // G1*HB_P
    float* h1buf = hbuf + G1 * HB_P;      // G1*T1

    const int tid  = threadIdx.x;
    const int base = blockIdx.x * G1;
    const int g    = tid;
    const int j    = tid & 63, q = tid >> 6;

    // fc1: h1[s][t] = x[s] . fc1_w[t] + fc1_b[t]
    for (int idx = tid; idx < G1 * T1; idx += 256) {
        int s = idx / T1, t = idx - s * T1;
        const float* xr = x + (base + s) * 20;
        const float* wr = fc1_w + t * 20;
        float acc = fc1_b[t];
        #pragma unroll
        for (int i = 0; i < 20; i++) acc = fmaf(xr[i], wr[i], acc);
        h1buf[s * T1 + t] = acc;
    }

    for (int d = 0; d < 2; d++) {
        const float* whh = d ? whh_b : whh_f;
        const float* wih = d ? wih_b : wih_f;
        const float* bg  = d ? b_b   : b_f;

        __syncthreads();
        for (int idx = tid; idx < G1 * HB_P; idx += 256) hbuf[idx] = 0.f;

        // weight-stationary: this thread's Whh row in registers
        float4 wv[16];
        const float4* wgp = (const float4*)(whh + g * 64);
        #pragma unroll
        for (int kc = 0; kc < 16; kc++) wv[kc] = __ldg(wgp + kc);
        const float wihg = __ldg(wih + g);
        const float bsg  = __ldg(bg + g);

        float c_reg[8];
        #pragma unroll
        for (int i = 0; i < 8; i++) c_reg[i] = 0.f;
        __syncthreads();

        const bool tanh_gate = ((g >> 6) == 2);

        for (int tt = 0; tt < T1; tt++) {
            const int t = d ? (T1 - 1 - tt) : tt;

            for (int sg = 0; sg < G1; sg += 2) {
                float a0 = fmaf(h1buf[(sg + 0) * T1 + t], wihg, bsg);
                float a1 = fmaf(h1buf[(sg + 1) * T1 + t], wihg, bsg);
                #pragma unroll
                for (int kc = 0; kc < 16; kc++) {
                    float4 w4 = wv[kc];
                    float4 h0 = *(const float4*)(hbuf + (sg + 0) * HB_P + kc * 4);
                    float4 h1 = *(const float4*)(hbuf + (sg + 1) * HB_P + kc * 4);
                    a0 = dot4acc(w4, h0, a0);
                    a1 = dot4acc(w4, h1, a1);
                }
                gact[(sg + 0) * GA_P + g] = tanh_gate ? ftanh_(a0) : fsig(a0);
                gact[(sg + 1) * GA_P + g] = tanh_gate ? ftanh_(a1) : fsig(a1);
            }
            __syncthreads();

            #pragma unroll
            for (int si = 0; si < 8; si++) {
                const int s = q + si * 4;
                float gi = gact[s * GA_P + j];
                float gf = gact[s * GA_P + 64 + j];
                float gg = gact[s * GA_P + 128 + j];
                float go = gact[s * GA_P + 192 + j];
                float c  = fmaf(gf, c_reg[si], gi * gg);
                c_reg[si] = c;
                float h = go * ftanh_(c);
                hbuf[s * HB_P + j] = h;
                g_seq1[((base + s) * T1 + t) * 128 + d * 64 + j] = h;
            }
            __syncthreads();
        }
    }
}

// ---------------------------------------------------------------------------
// Kernel 2: bidirectional LSTM layer 2 + fc2 + tanh.
// 512 threads: two 256-gate halves, each owning 8 of the 16 samples.
// Input-proj weights transposed in SMEM -> conflict-free, loaded once per step.
// ---------------------------------------------------------------------------
__global__ __launch_bounds__(512, 1)
void k_layer2(const float* __restrict__ wih2_f, const float* __restrict__ whh2_f, const float* __restrict__ b2_f,
              const float* __restrict__ wih2_b, const float* __restrict__ whh2_b, const float* __restrict__ b2_b,
              const float* __restrict__ fc2_w, const float* __restrict__ fc2_b,
              float* __restrict__ out)
{
    extern __shared__ float sm[];
    float* wih_sT = sm;                      // 128*WT_P  (transposed: [k][g])
    float* xgb    = wih_sT + 128 * WT_P;     // G2*GA_P   (cached input projection)
    float* gact   = xgb  + G2 * GA_P;        // G2*GA_P
    float* hbuf   = gact + G2 * GA_P;        // G2*HB_P
    float* inbuf  = hbuf + G2 * HB_P;        // G2*128
    float* outac  = inbuf + G2 * 128;        // G2*T2  (fwd fc2 partial dots)
    float* fc2_s  = outac + G2 * T2;         // 128

    const int tid  = threadIdx.x;
    const int base = blockIdx.x * G2;
    const int g    = tid & 255;            // gate id
    const int half = tid >> 8;             // 0 or 1: which 8 samples
    const int s0   = half * 8;
    const int j    = tid & 63, q = tid >> 6;   // q in 0..7 (state update)
    const int wrp  = tid >> 5, lan = tid & 31; // 16 warps (fc2)

    if (tid < 128) fc2_s[tid] = fc2_w[tid];
    const float fc2b = __ldg(fc2_b);

    for (int d = 0; d < 2; d++) {
        const float* whh = d ? whh2_b : whh2_f;
        const float* wih = d ? wih2_b : wih2_f;
        const float* bg  = d ? b2_b   : b2_f;

        __syncthreads();
        // stage input-projection weights TRANSPOSED: wih_sT[k][g] = wih[g][k]
        // write: lanes have consecutive k at fixed g -> stride WT_P=257 ≡ 1 mod 32 -> conflict-free
        for (int idx = tid; idx < 256 * 128; idx += 512) {
            int gg = idx >> 7, kk = idx & 127;
            wih_sT[kk * WT_P + gg] = wih[idx];
        }
        for (int idx = tid; idx < G2 * HB_P; idx += 512) hbuf[idx] = 0.f;

        // recurrent weights: this thread's Whh row in registers
        float4 wv[16];
        const float4* wgp = (const float4*)(whh + g * 64);
        #pragma unroll
        for (int kc = 0; kc < 16; kc++) wv[kc] = __ldg(wgp + kc);
        const float bsg = __ldg(bg + g);

        float c_reg[2] = {0.f, 0.f};
        __syncthreads();

        const bool tanh_gate = ((g >> 6) == 2);

        for (int tt = 0; tt < T2; tt++) {
            const int t = d ? (T2 - 1 - tt) : tt;

            // first visit of each repeated pair: load input + compute projection
            if ((tt & 1) == 0) {
                const int m = t >> 1;
                for (int idx = tid; idx < G2 * 32; idx += 512) {
                    int s = idx >> 5, i = idx & 31;
                    ((float4*)inbuf)[idx] =
                        ((const float4*)(g_seq1 + ((base + s) * T1 + m) * 128))[i];
                }
                __syncthreads();

                // k-outer, 8-sample accumulators: each weight loaded ONCE,
                // conflict-free scalar LDS; sample vectors are warp-broadcast.
                float a[8];
                #pragma unroll
                for (int ss = 0; ss < 8; ss++) a[ss] = bsg;
                #pragma unroll 4
                for (int k = 0; k < 128; k += 4) {
                    float w0 = wih_sT[(k + 0) * WT_P + g];
                    float w1 = wih_sT[(k + 1) * WT_P + g];
                    float w2 = wih_sT[(k + 2) * WT_P + g];
                    float w3 = wih_sT[(k + 3) * WT_P + g];
                    #pragma unroll
                    for (int ss = 0; ss < 8; ss++) {
                        float4 in4 = *(const float4*)(inbuf + (s0 + ss) * 128 + k);
                        float av = a[ss];
                        av = fmaf(in4.x, w0, av);
                        av = fmaf(in4.y, w1, av);
                        av = fmaf(in4.z, w2, av);
                        a[ss] = fmaf(in4.w, w3, av);
                    }
                }
                #pragma unroll
                for (int ss = 0; ss < 8; ss++)
                    xgb[(s0 + ss) * GA_P + g] = a[ss];   // same-thread reuse only
            }

            // recurrence: gates = xg + Whh @ h   (weights in regs, h broadcast)
            for (int sg = s0; sg < s0 + 8; sg += 2) {
                float a0 = xgb[(sg + 0) * GA_P + g];
                float a1 = xgb[(sg + 1) * GA_P + g];
                #pragma unroll
                for (int kc = 0; kc < 16; kc++) {
                    float4 w4 = wv[kc];
                    float4 h0 = *(const float4*)(hbuf + (sg + 0) * HB_P + kc * 4);
                    float4 h1 = *(const float4*)(hbuf + (sg + 1) * HB_P + kc * 4);
                    a0 = dot4acc(w4, h0, a0);
                    a1 = dot4acc(w4, h1, a1);
                }
                gact[(sg + 0) * GA_P + g] = tanh_gate ? ftanh_(a0) : fsig(a0);
                gact[(sg + 1) * GA_P + g] = tanh_gate ? ftanh_(a1) : fsig(a1);
            }
            __syncthreads();

            // state update: thread (j,q) owns hidden unit j of samples q, q+8
            #pragma unroll
            for (int si = 0; si < 2; si++) {
                const int s = q + si * 8;
                float gi = gact[s * GA_P + j];
                float gf = gact[s * GA_P + 64 + j];
                float gg = gact[s * GA_P + 128 + j];
                float go = gact[s * GA_P + 192 + j];
                float c  = fmaf(gf, c_reg[si], gi * gg);
                c_reg[si] = c;
                hbuf[s * HB_P + j] = go * ftanh_(c);
            }
            __syncthreads();

            // fc2 partial dot: warp wrp owns sample wrp
            {
                const int s = wrp;
                float p = hbuf[s * HB_P + lan]      * fc2_s[d * 64 + lan]
                        + hbuf[s * HB_P + 32 + lan] * fc2_s[d * 64 + 32 + lan];
                #pragma unroll
                for (int o = 16; o > 0; o >>= 1)
                    p += __shfl_down_sync(0xffffffffu, p, o);
                if (lan == 0) {
                    if (d == 0) outac[s * T2 + t] = p;
                    else out[(base + s) * T2 + t] = ftanh_(outac[s * T2 + t] + p + fc2b);
                }
            }
        }
    }
}

// ---------------------------------------------------------------------------
extern "C" void kernel_launch(void* const* d_in, const int* in_sizes, int n_in,
                              void* d_out, int out_size)
{
    const float* x    = (const float*)d_in[0];
    const float* fc1w = (const float*)d_in[1];
    const float* fc1b = (const float*)d_in[2];
    const float* r1wf = (const float*)d_in[3];
    const float* r1hf = (const float*)d_in[4];
    const float* r1bf = (const float*)d_in[5];
    const float* r1wb = (const float*)d_in[6];
    const float* r1hb = (const float*)d_in[7];
    const float* r1bb = (const float*)d_in[8];
    const float* r2wf = (const float*)d_in[9];
    const float* r2hf = (const float*)d_in[10];
    const float* r2bf = (const float*)d_in[11];
    const float* r2wb = (const float*)d_in[12];
    const float* r2hb = (const float*)d_in[13];
    const float* r2bb = (const float*)d_in[14];
    const float* fc2w = (const float*)d_in[15];
    const float* fc2b = (const float*)d_in[16];
    float* out = (float*)d_out;

    const size_t SM1 = (size_t)(G1 * GA_P + G1 * HB_P + G1 * T1) * sizeof(float);
    const size_t SM2 = (size_t)(128 * WT_P + 2 * G2 * GA_P + G2 * HB_P +
                                G2 * 128 + G2 * T2 + 128) * sizeof(float);

    cudaFuncSetAttribute(k_layer1, cudaFuncAttributeMaxDynamicSharedMemorySize, (int)SM1);
    cudaFuncSetAttribute(k_layer2, cudaFuncAttributeMaxDynamicSharedMemorySize, (int)SM2);

    k_layer1<<<BT / G1, 256, SM1>>>(x, fc1w, fc1b, r1wf, r1hf, r1bf, r1wb, r1hb, r1bb);
    k_layer2<<<BT / G2, 512, SM2>>>(r2wf, r2hf, r2bf, r2wb, r2hb, r2bb, fc2w, fc2b, out);
}